// round 7
// baseline (speedup 1.0000x reference)
#include <cuda_runtime.h>
#include <cstdint>

#define RR 16384      // B*L rows
#define KK 4096       // clusters
#define DD 512        // feature dim
#define QELEMS (RR * DD)          // 8388608
#define LOSS_OFF QELEMS           // 8388608
#define IDX_OFF  (QELEMS + 1)     // 8388609

// ---- scratch (device globals: no allocation allowed) ----
__device__ float              g_c2[KK];
__device__ float              g_x2[RR];
__device__ unsigned long long g_best[RR];
__device__ int                g_counts[KK];
__device__ float              g_dw[KK * DD];          // 8 MB
__device__ float              g_avg_cluster[KK];
__device__ float              g_codebook_new[KK * DD]; // 8 MB
__device__ float              g_Nsum;

// ---------------------------------------------------------------------------
// 0) init: zero dw/counts/Nsum, set best = MAX, zero loss slot
// ---------------------------------------------------------------------------
__global__ void vq_init(float* out) {
    int i = blockIdx.x * blockDim.x + threadIdx.x;   // 524288 threads
    ((float4*)g_dw)[i] = make_float4(0.f, 0.f, 0.f, 0.f);
    if (i < RR) g_best[i] = 0xFFFFFFFFFFFFFFFFull;
    if (i < KK) g_counts[i] = 0;
    if (i == 0) { g_Nsum = 0.f; out[LOSS_OFF] = 0.f; }
}

// ---------------------------------------------------------------------------
// 1) squared norms: rows 0..KK-1 -> c2(codebook), rows KK.. -> x2(x)
// ---------------------------------------------------------------------------
__global__ void vq_sqnorm(const float* __restrict__ x, const float* __restrict__ cb) {
    int warp = (blockIdx.x * blockDim.x + threadIdx.x) >> 5;   // 20480 warps
    int lane = threadIdx.x & 31;
    const float* src;
    if (warp < KK) src = cb + (size_t)warp * DD;
    else           src = x + (size_t)(warp - KK) * DD;
    const float4* s4 = (const float4*)src;
    float s = 0.f;
#pragma unroll
    for (int w = 0; w < 4; w++) {
        float4 v = s4[lane + 32 * w];
        s += v.x * v.x + v.y * v.y + v.z * v.z + v.w * v.w;
    }
#pragma unroll
    for (int o = 16; o; o >>= 1) s += __shfl_xor_sync(0xFFFFFFFFu, s, o);
    if (lane == 0) {
        if (warp < KK) g_c2[warp] = s;
        else           g_x2[warp - KK] = s;
    }
}

// ---------------------------------------------------------------------------
// 2) fused 128x128x512 fp32 GEMM + per-row argmin of (x2 - 2*xc) + c2
//    grid = (KK/128, RR/128), 256 threads, 8x8 micro-tile, double-buffered smem
// ---------------------------------------------------------------------------
__global__ __launch_bounds__(256, 2)
void vq_argmin_gemm(const float* __restrict__ X, const float* __restrict__ C) {
    __shared__ float As[2][8][128];
    __shared__ float Bs[2][8][128];
    __shared__ unsigned long long sbest[128];

    const int t  = threadIdx.x;
    const int tx = t & 15;
    const int ty = t >> 4;
    const int row0 = blockIdx.y * 128;
    const int col0 = blockIdx.x * 128;

    if (t < 128) sbest[t] = 0xFFFFFFFFFFFFFFFFull;

    // global->smem transpose loaders: thread loads one float4 of a 128x8 slab
    const int lr = t >> 1;          // 0..127 (row within tile)
    const int lc = (t & 1) * 4;     // 0 or 4 (d offset within k-slab)
    const float* Xg = X + (size_t)(row0 + lr) * DD + lc;
    const float* Cg = C + (size_t)(col0 + lr) * DD + lc;

    float acc[8][8];
#pragma unroll
    for (int i = 0; i < 8; i++)
#pragma unroll
        for (int j = 0; j < 8; j++) acc[i][j] = 0.f;

    {
        float4 va = *(const float4*)Xg;
        float4 vb = *(const float4*)Cg;
        As[0][lc + 0][lr] = va.x; As[0][lc + 1][lr] = va.y;
        As[0][lc + 2][lr] = va.z; As[0][lc + 3][lr] = va.w;
        Bs[0][lc + 0][lr] = vb.x; Bs[0][lc + 1][lr] = vb.y;
        Bs[0][lc + 2][lr] = vb.z; Bs[0][lc + 3][lr] = vb.w;
    }
    __syncthreads();

    int buf = 0;
    for (int kt = 8; kt <= DD; kt += 8) {
        float4 na, nb;
        const bool more = (kt < DD);
        if (more) { na = *(const float4*)(Xg + kt); nb = *(const float4*)(Cg + kt); }

#pragma unroll
        for (int kk = 0; kk < 8; kk++) {
            float a[8], b[8];
            float4 t0 = *(const float4*)&As[buf][kk][ty * 4];
            float4 t1 = *(const float4*)&As[buf][kk][64 + ty * 4];
            float4 u0 = *(const float4*)&Bs[buf][kk][tx * 4];
            float4 u1 = *(const float4*)&Bs[buf][kk][64 + tx * 4];
            a[0]=t0.x; a[1]=t0.y; a[2]=t0.z; a[3]=t0.w;
            a[4]=t1.x; a[5]=t1.y; a[6]=t1.z; a[7]=t1.w;
            b[0]=u0.x; b[1]=u0.y; b[2]=u0.z; b[3]=u0.w;
            b[4]=u1.x; b[5]=u1.y; b[6]=u1.z; b[7]=u1.w;
#pragma unroll
            for (int i = 0; i < 8; i++)
#pragma unroll
                for (int j = 0; j < 8; j++)
                    acc[i][j] = fmaf(a[i], b[j], acc[i][j]);
        }

        if (more) {
            const int nbuf = buf ^ 1;
            As[nbuf][lc + 0][lr] = na.x; As[nbuf][lc + 1][lr] = na.y;
            As[nbuf][lc + 2][lr] = na.z; As[nbuf][lc + 3][lr] = na.w;
            Bs[nbuf][lc + 0][lr] = nb.x; Bs[nbuf][lc + 1][lr] = nb.y;
            Bs[nbuf][lc + 2][lr] = nb.z; Bs[nbuf][lc + 3][lr] = nb.w;
        }
        __syncthreads();
        buf ^= 1;
    }

    // epilogue: dist = (x2 - 2*xc) + c2  (same evaluation shape as reference)
    float x2r[8], c2c[8];
    int   kidx[8];
#pragma unroll
    for (int i = 0; i < 4; i++) {
        x2r[i]     = g_x2[row0 + ty * 4 + i];
        x2r[4 + i] = g_x2[row0 + 64 + ty * 4 + i];
        kidx[i]     = col0 + tx * 4 + i;
        kidx[4 + i] = col0 + 64 + tx * 4 + i;
        c2c[i]     = g_c2[kidx[i]];
        c2c[4 + i] = g_c2[kidx[4 + i]];
    }
#pragma unroll
    for (int i = 0; i < 8; i++) {
        float bd = (x2r[i] - 2.0f * acc[i][0]) + c2c[0];
        int   bk = kidx[0];
#pragma unroll
        for (int j = 1; j < 8; j++) {
            float d = (x2r[i] - 2.0f * acc[i][j]) + c2c[j];
            if (d < bd) { bd = d; bk = kidx[j]; }   // strict <: first index wins ties
        }
        unsigned int u = __float_as_uint(bd);
        u = (u & 0x80000000u) ? ~u : (u | 0x80000000u);  // order-preserving map
        unsigned long long key = ((unsigned long long)u << 32) | (unsigned int)bk;
        int lrow = (i < 4) ? (ty * 4 + i) : (64 + ty * 4 + (i - 4));
        atomicMin(&sbest[lrow], key);
    }
    __syncthreads();
    if (t < 128) atomicMin(&g_best[row0 + t], sbest[t]);
}

// ---------------------------------------------------------------------------
// 3) scatter: counts + dw, 2 rows per 256-thread block (128 threads per row)
// ---------------------------------------------------------------------------
__global__ void vq_scatter(const float* __restrict__ X) {
    int row  = blockIdx.x * 2 + (threadIdx.x >> 7);
    int lane = threadIdx.x & 127;
    int idx  = (int)(g_best[row] & 0xFFFFFFFFull);
    if (lane == 0) atomicAdd(&g_counts[idx], 1);
    float4 v = ((const float4*)(X + (size_t)row * DD))[lane];
    float* dst = g_dw + (size_t)idx * DD + lane * 4;
    atomicAdd(dst + 0, v.x);
    atomicAdd(dst + 1, v.y);
    atomicAdd(dst + 2, v.z);
    atomicAdd(dst + 3, v.w);
}

// ---------------------------------------------------------------------------
// 4) per-cluster EMA stats: avg_cluster + Nsum
// ---------------------------------------------------------------------------
__global__ void vq_stats(const float* __restrict__ hc, const float* __restrict__ cntp) {
    const float OMD = 1.0f - 0.99f;
    int k = blockIdx.x * 256 + threadIdx.x;
    float bias = 1.0f - powf(0.99f, cntp[0] + 1.0f);
    float avg = (hc[k] * 0.99f + OMD * (float)g_counts[k]) / bias;
    g_avg_cluster[k] = avg;

    float s = avg;
#pragma unroll
    for (int o = 16; o; o >>= 1) s += __shfl_xor_sync(0xFFFFFFFFu, s, o);
    __shared__ float sred[8];
    if ((threadIdx.x & 31) == 0) sred[threadIdx.x >> 5] = s;
    __syncthreads();
    if (threadIdx.x == 0) {
        float tot = 0.f;
#pragma unroll
        for (int w = 0; w < 8; w++) tot += sred[w];
        atomicAdd(&g_Nsum, tot);
    }
}

// ---------------------------------------------------------------------------
// 5) codebook_new[k,d] = ((hdw*decay + (1-decay)*dw)/bias) / cc[k]
// ---------------------------------------------------------------------------
__global__ void vq_codebook(const float* __restrict__ hdw, const float* __restrict__ cntp) {
    const float OMD = 1.0f - 0.99f;
    const float EPSc = 1e-5f;
    int i4 = blockIdx.x * blockDim.x + threadIdx.x;   // 524288 float4s
    int k = i4 >> 7;
    float bias = 1.0f - powf(0.99f, cntp[0] + 1.0f);
    float N = g_Nsum;
    float cc = (g_avg_cluster[k] + EPSc) / (N + (float)KK * EPSc) * N;
    float4 h = ((const float4*)hdw)[i4];
    float4 w = ((const float4*)g_dw)[i4];
    float4 o;
    o.x = ((h.x * 0.99f + OMD * w.x) / bias) / cc;
    o.y = ((h.y * 0.99f + OMD * w.y) / bias) / cc;
    o.z = ((h.z * 0.99f + OMD * w.z) / bias) / cc;
    o.w = ((h.w * 0.99f + OMD * w.w) / bias) / cc;
    ((float4*)g_codebook_new)[i4] = o;
}

// ---------------------------------------------------------------------------
// 6) gather quantized = x + (q - x), loss partials, indices
// ---------------------------------------------------------------------------
__global__ void vq_gather(const float* __restrict__ X, float* __restrict__ out) {
    int row  = blockIdx.x;              // 16384 blocks x 128 threads
    int lane = threadIdx.x;
    int idx  = (int)(g_best[row] & 0xFFFFFFFFull);

    float4 xv = ((const float4*)(X + (size_t)row * DD))[lane];
    float4 qv = ((const float4*)(g_codebook_new + (size_t)idx * DD))[lane];
    float4 o;
    o.x = xv.x + (qv.x - xv.x);
    o.y = xv.y + (qv.y - xv.y);
    o.z = xv.z + (qv.z - xv.z);
    o.w = xv.w + (qv.w - xv.w);
    ((float4*)out)[row * 128 + lane] = o;

    float dx = xv.x - o.x, dy = xv.y - o.y, dz = xv.z - o.z, dw_ = xv.w - o.w;
    float s = dx * dx + dy * dy + dz * dz + dw_ * dw_;
#pragma unroll
    for (int off = 16; off; off >>= 1) s += __shfl_xor_sync(0xFFFFFFFFu, s, off);
    __shared__ float sred[4];
    if ((lane & 31) == 0) sred[lane >> 5] = s;
    __syncthreads();
    if (lane == 0) {
        float tot = sred[0] + sred[1] + sred[2] + sred[3];
        atomicAdd(out + LOSS_OFF, tot * (0.5f / (float)QELEMS));
        out[IDX_OFF + row] = (float)idx;
    }
}

// ---------------------------------------------------------------------------
extern "C" void kernel_launch(void* const* d_in, const int* in_sizes, int n_in,
                              void* d_out, int out_size) {
    const float* x    = (const float*)d_in[0];   // (8,2048,512)
    const float* cb   = (const float*)d_in[1];   // (4096,512)
    const float* hc   = (const float*)d_in[2];   // (4096,)
    const float* hdw  = (const float*)d_in[3];   // (4096,512)
    const float* cnt  = (const float*)d_in[4];   // scalar
    float* out = (float*)d_out;

    vq_init<<<2048, 256>>>(out);                         // 524288 threads
    vq_sqnorm<<<(KK + RR) / 8, 256>>>(x, cb);            // 2560 blocks, 8 warps each
    vq_argmin_gemm<<<dim3(KK / 128, RR / 128), 256>>>(x, cb);
    vq_scatter<<<RR / 2, 256>>>(x);
    vq_stats<<<KK / 256, 256>>>(hc, cnt);
    vq_codebook<<<(KK * DD / 4) / 256, 256>>>(hdw, cnt);
    vq_gather<<<RR, 128>>>(x, out);
}

// round 11
// speedup vs baseline: 1.2955x; 1.2955x over previous
#include <cuda_runtime.h>
#include <cstdint>

#define RR 16384      // B*L rows
#define KK 4096       // clusters
#define DD 512        // feature dim
#define QELEMS (RR * DD)          // 8388608
#define LOSS_OFF QELEMS
#define IDX_OFF  (QELEMS + 1)

// ---- scratch (device globals: no allocation allowed) ----
__device__ float              g_c2[KK];
__device__ float              g_x2[RR];
__device__ unsigned long long g_best[RR];
__device__ int                g_counts[KK];
__device__ float              g_dw[KK * DD];            // 8 MB
__device__ float              g_avg_cluster[KK];
__device__ float              g_codebook_new[KK * DD];  // 8 MB
__device__ float              g_Nsum;
__device__ ulonglong2         g_tb[RR * 128];           // 32 MB: per-row top2 per 32-col group

// ---------------------------------------------------------------------------
// helpers
// ---------------------------------------------------------------------------
__device__ __forceinline__ uint32_t smem_u32(const void* p) {
    uint32_t a;
    asm("{ .reg .u64 t; cvta.to.shared.u64 t, %1; cvt.u32.u64 %0, t; }"
        : "=r"(a) : "l"(p));
    return a;
}

__device__ __forceinline__ unsigned long long packkey(float d, int k) {
    unsigned int u = __float_as_uint(d);
    u = (u & 0x80000000u) ? ~u : (u | 0x80000000u);   // order-preserving map
    return ((unsigned long long)u << 32) | (unsigned int)k;
}

__device__ __forceinline__ float decf(uint32_t u) {
    uint32_t x = (u & 0x80000000u) ? (u & 0x7FFFFFFFu) : ~u;
    return __uint_as_float(x);
}

// merge two (top1,top2) pairs -> top2 of union
__device__ __forceinline__ void top2merge(unsigned long long& p1, unsigned long long& p2,
                                          unsigned long long q1, unsigned long long q2) {
    unsigned long long n1 = p1 < q1 ? p1 : q1;
    unsigned long long hi = p1 < q1 ? q1 : p1;
    unsigned long long l2 = p2 < q2 ? p2 : q2;
    p1 = n1;
    p2 = hi < l2 ? hi : l2;
}

// ---------------------------------------------------------------------------
// 0) init
// ---------------------------------------------------------------------------
__global__ void vq_init(float* out) {
    int i = blockIdx.x * blockDim.x + threadIdx.x;   // 524288 threads
    ((float4*)g_dw)[i] = make_float4(0.f, 0.f, 0.f, 0.f);
    if (i < KK) g_counts[i] = 0;
    if (i == 0) { g_Nsum = 0.f; out[LOSS_OFF] = 0.f; }
}

// ---------------------------------------------------------------------------
// 1) squared norms: rows 0..KK-1 -> c2(codebook), rows KK.. -> x2(x)
// ---------------------------------------------------------------------------
__global__ void vq_sqnorm(const float* __restrict__ x, const float* __restrict__ cb) {
    int warp = (blockIdx.x * blockDim.x + threadIdx.x) >> 5;   // 20480 warps
    int lane = threadIdx.x & 31;
    const float* src;
    if (warp < KK) src = cb + (size_t)warp * DD;
    else           src = x + (size_t)(warp - KK) * DD;
    const float4* s4 = (const float4*)src;
    float s = 0.f;
#pragma unroll
    for (int w = 0; w < 4; w++) {
        float4 v = s4[lane + 32 * w];
        s += v.x * v.x + v.y * v.y + v.z * v.z + v.w * v.w;
    }
#pragma unroll
    for (int o = 16; o; o >>= 1) s += __shfl_xor_sync(0xFFFFFFFFu, s, o);
    if (lane == 0) {
        if (warp < KK) g_c2[warp] = s;
        else           g_x2[warp - KK] = s;
    }
}

// ---------------------------------------------------------------------------
// 2) tf32 HMMA GEMM (mma.sync m16n8k8) + fused per-row top-2 per 32-col group
//    CTA tile 128x256, 8 warps of 64x64, K staged 32 wide, cp.async 2-buffer
// ---------------------------------------------------------------------------
#define TM 128
#define TN 256
#define TKS 32
#define NST (DD / TKS)           // 16
#define APAD 36                  // row stride in floats (conflict-free)
#define A_FLOATS (TM * APAD)     // 4608
#define B_FLOATS (TN * APAD)     // 9216
#define SM_A 1024
#define SM_B (SM_A + 2 * A_FLOATS * 4)        // 37888
#define GEMM_SMEM (SM_B + 2 * B_FLOATS * 4)   // 111616

__device__ __forceinline__ void stage_load(const float* __restrict__ X,
                                           const float* __restrict__ C,
                                           uint32_t sA, uint32_t sB,
                                           int row0, int col0, int kt, int t) {
#pragma unroll
    for (int i = 0; i < 4; i++) {           // A: 128 rows x 32 k = 1024 16B chunks
        int ch = t + i * 256;
        int r = ch >> 3, c4 = (ch & 7) * 4;
        uint32_t dst = sA + (uint32_t)(r * APAD + c4) * 4u;
        const float* src = X + (size_t)(row0 + r) * DD + kt + c4;
        asm volatile("cp.async.cg.shared.global [%0], [%1], 16;"
                     :: "r"(dst), "l"(src) : "memory");
    }
#pragma unroll
    for (int i = 0; i < 8; i++) {           // B: 256 rows x 32 k = 2048 chunks
        int ch = t + i * 256;
        int r = ch >> 3, c4 = (ch & 7) * 4;
        uint32_t dst = sB + (uint32_t)(r * APAD + c4) * 4u;
        const float* src = C + (size_t)(col0 + r) * DD + kt + c4;
        asm volatile("cp.async.cg.shared.global [%0], [%1], 16;"
                     :: "r"(dst), "l"(src) : "memory");
    }
}

__global__ __launch_bounds__(256, 1)
void vq_mma(const float* __restrict__ X, const float* __restrict__ C) {
    extern __shared__ char sm[];
    float* c2s = (float*)sm;                 // [256]
    const uint32_t smb = smem_u32(sm);
    const int t = threadIdx.x, lane = t & 31, warp = t >> 5;
    const int wm = warp >> 2, wn = warp & 3;
    const int row0 = blockIdx.y * TM, col0 = blockIdx.x * TN;

    c2s[t] = g_c2[col0 + t];

    float acc[4][8][4];
#pragma unroll
    for (int a = 0; a < 4; a++)
#pragma unroll
        for (int b = 0; b < 8; b++)
#pragma unroll
            for (int c = 0; c < 4; c++) acc[a][b][c] = 0.f;

    stage_load(X, C, smb + SM_A, smb + SM_B, row0, col0, 0, t);
    asm volatile("cp.async.commit_group;" ::: "memory");

    for (int s = 0; s < NST; s++) {
        if (s + 1 < NST)
            stage_load(X, C,
                       smb + SM_A + (uint32_t)(((s + 1) & 1) * A_FLOATS * 4),
                       smb + SM_B + (uint32_t)(((s + 1) & 1) * B_FLOATS * 4),
                       row0, col0, (s + 1) * TKS, t);
        asm volatile("cp.async.commit_group;" ::: "memory");
        asm volatile("cp.async.wait_group 1;" ::: "memory");
        __syncthreads();

        const float* As_s = (const float*)(sm + SM_A + (s & 1) * A_FLOATS * 4);
        const float* Bs_s = (const float*)(sm + SM_B + (s & 1) * B_FLOATS * 4);

#pragma unroll
        for (int ks = 0; ks < 4; ks++) {
            const int k8 = ks * 8;
            uint32_t a0[4], a1[4], a2[4], a3[4], b0[8], b1[8];
#pragma unroll
            for (int mf = 0; mf < 4; mf++) {
                const float* p = As_s + (wm * 64 + mf * 16 + (lane >> 2)) * APAD
                               + k8 + (lane & 3);
                a0[mf] = __float_as_uint(p[0]);
                a2[mf] = __float_as_uint(p[4]);
                a1[mf] = __float_as_uint(p[8 * APAD]);
                a3[mf] = __float_as_uint(p[8 * APAD + 4]);
            }
#pragma unroll
            for (int nf = 0; nf < 8; nf++) {
                const float* p = Bs_s + (wn * 64 + nf * 8 + (lane >> 2)) * APAD
                               + k8 + (lane & 3);
                b0[nf] = __float_as_uint(p[0]);
                b1[nf] = __float_as_uint(p[4]);
            }
#pragma unroll
            for (int mf = 0; mf < 4; mf++)
#pragma unroll
                for (int nf = 0; nf < 8; nf++)
                    asm volatile(
                        "mma.sync.aligned.m16n8k8.row.col.f32.tf32.tf32.f32 "
                        "{%0,%1,%2,%3}, {%4,%5,%6,%7}, {%8,%9}, {%0,%1,%2,%3};"
                        : "+f"(acc[mf][nf][0]), "+f"(acc[mf][nf][1]),
                          "+f"(acc[mf][nf][2]), "+f"(acc[mf][nf][3])
                        : "r"(a0[mf]), "r"(a1[mf]), "r"(a2[mf]), "r"(a3[mf]),
                          "r"(b0[nf]), "r"(b1[nf]));
        }
        __syncthreads();
    }

    // epilogue: per-row top-2 within each 32-col group (2 groups per warp tile)
    // acc frag val v: row = rs*8 + lane>>2 (rs = v>>1), col = (lane&3)*2 + (v&1)
#pragma unroll
    for (int mf = 0; mf < 4; mf++) {
#pragma unroll
        for (int rs = 0; rs < 2; rs++) {
#pragma unroll
            for (int h = 0; h < 2; h++) {       // 32-col half of the 64-col warp tile
                unsigned long long p1 = ~0ull, p2 = ~0ull;
#pragma unroll
                for (int nf = h * 4; nf < h * 4 + 4; nf++) {
#pragma unroll
                    for (int j = 0; j < 2; j++) {
                        int lc = wn * 64 + nf * 8 + (lane & 3) * 2 + j;
                        float d = c2s[lc] - 2.0f * acc[mf][nf][rs * 2 + j];
                        unsigned long long key = packkey(d, col0 + lc);
                        if (key < p1) { p2 = p1; p1 = key; }
                        else if (key < p2) p2 = key;
                    }
                }
#pragma unroll
                for (int off = 1; off <= 2; off <<= 1) {
                    unsigned long long q1 = __shfl_xor_sync(0xFFFFFFFFu, p1, off);
                    unsigned long long q2 = __shfl_xor_sync(0xFFFFFFFFu, p2, off);
                    top2merge(p1, p2, q1, q2);
                }
                if ((lane & 3) == 0) {
                    int row = row0 + wm * 64 + mf * 16 + rs * 8 + (lane >> 2);
                    g_tb[row * 128 + blockIdx.x * 8 + wn * 2 + h] =
                        make_ulonglong2(p1, p2);
                }
            }
        }
    }
}

// ---------------------------------------------------------------------------
// 2b) rescue: gap-gated exact fp32 rescoring of the 256 candidates per row
//     exact shape matches reference: (x2 - 2*dot) + c2
// ---------------------------------------------------------------------------
#define TAU 0.025f

__global__ void vq_rescue(const float* __restrict__ X, const float* __restrict__ C) {
    const int row = blockIdx.x;          // 16384 blocks x 128 threads
    const int t = threadIdx.x;
    const int lane = t & 31, warp = t >> 5;
    __shared__ float xs[DD];
    __shared__ unsigned long long red[128];
    __shared__ unsigned long long wtop[4][2];
    __shared__ int flag;

    ulonglong2 mine = g_tb[row * 128 + t];
    ((float4*)xs)[t] = ((const float4*)X)[row * 128 + t];

    // block-wide top-2 of the 256 candidate keys (for the gap gate)
    unsigned long long p1 = mine.x < mine.y ? mine.x : mine.y;
    unsigned long long p2 = mine.x < mine.y ? mine.y : mine.x;
#pragma unroll
    for (int off = 16; off; off >>= 1) {
        unsigned long long q1 = __shfl_xor_sync(0xFFFFFFFFu, p1, off);
        unsigned long long q2 = __shfl_xor_sync(0xFFFFFFFFu, p2, off);
        top2merge(p1, p2, q1, q2);
    }
    if (lane == 0) { wtop[warp][0] = p1; wtop[warp][1] = p2; }
    __syncthreads();
    if (t == 0) {
        unsigned long long b1 = wtop[0][0], b2 = wtop[0][1];
        top2merge(b1, b2, wtop[1][0], wtop[1][1]);
        top2merge(b1, b2, wtop[2][0], wtop[2][1]);
        top2merge(b1, b2, wtop[3][0], wtop[3][1]);
        float gap = decf((uint32_t)(b2 >> 32)) - decf((uint32_t)(b1 >> 32));
        flag = (gap < TAU);
        if (!flag) g_best[row] = b1;     // approx argmin provably exact
    }
    __syncthreads();
    if (!flag) return;

    // exact fp32 rescore of this thread's 2 candidates
    const float x2r = g_x2[row];
    unsigned long long best = ~0ull;
    const float4* x4 = (const float4*)xs;
#pragma unroll
    for (int cidx = 0; cidx < 2; cidx++) {
        int k = (int)((cidx ? mine.y : mine.x) & 0xFFFFFFFFu);
        const float4* c4 = (const float4*)(C + (size_t)k * DD);
        float d0 = 0.f, d1 = 0.f, d2 = 0.f, d3 = 0.f;
#pragma unroll 8
        for (int i = 0; i < 128; i++) {
            float4 a = x4[i], b = c4[i];
            d0 = fmaf(a.x, b.x, d0); d1 = fmaf(a.y, b.y, d1);
            d2 = fmaf(a.z, b.z, d2); d3 = fmaf(a.w, b.w, d3);
        }
        float dot = (d0 + d1) + (d2 + d3);
        unsigned long long key = packkey((x2r - 2.0f * dot) + g_c2[k], k);
        if (key < best) best = key;
    }
    red[t] = best;
    __syncthreads();
    for (int s = 64; s; s >>= 1) {
        if (t < s) red[t] = red[t] < red[t + s] ? red[t] : red[t + s];
        __syncthreads();
    }
    if (t == 0) g_best[row] = red[0];
}

// ---------------------------------------------------------------------------
// 3) scatter: counts + dw
// ---------------------------------------------------------------------------
__global__ void vq_scatter(const float* __restrict__ X) {
    int row  = blockIdx.x * 2 + (threadIdx.x >> 7);
    int lane = threadIdx.x & 127;
    int idx  = (int)(g_best[row] & 0xFFFFFFFFull);
    if (lane == 0) atomicAdd(&g_counts[idx], 1);
    float4 v = ((const float4*)(X + (size_t)row * DD))[lane];
    float* dst = g_dw + (size_t)idx * DD + lane * 4;
    atomicAdd(dst + 0, v.x);
    atomicAdd(dst + 1, v.y);
    atomicAdd(dst + 2, v.z);
    atomicAdd(dst + 3, v.w);
}

// ---------------------------------------------------------------------------
// 4) per-cluster EMA stats: avg_cluster + Nsum
// ---------------------------------------------------------------------------
__global__ void vq_stats(const float* __restrict__ hc, const float* __restrict__ cntp) {
    const float OMD = 1.0f - 0.99f;
    int k = blockIdx.x * 256 + threadIdx.x;
    float bias = 1.0f - powf(0.99f, cntp[0] + 1.0f);
    float avg = (hc[k] * 0.99f + OMD * (float)g_counts[k]) / bias;
    g_avg_cluster[k] = avg;

    float s = avg;
#pragma unroll
    for (int o = 16; o; o >>= 1) s += __shfl_xor_sync(0xFFFFFFFFu, s, o);
    __shared__ float sred[8];
    if ((threadIdx.x & 31) == 0) sred[threadIdx.x >> 5] = s;
    __syncthreads();
    if (threadIdx.x == 0) {
        float tot = 0.f;
#pragma unroll
        for (int w = 0; w < 8; w++) tot += sred[w];
        atomicAdd(&g_Nsum, tot);
    }
}

// ---------------------------------------------------------------------------
// 5) codebook_new
// ---------------------------------------------------------------------------
__global__ void vq_codebook(const float* __restrict__ hdw, const float* __restrict__ cntp) {
    const float OMD = 1.0f - 0.99f;
    const float EPSc = 1e-5f;
    int i4 = blockIdx.x * blockDim.x + threadIdx.x;   // 524288 float4s
    int k = i4 >> 7;
    float bias = 1.0f - powf(0.99f, cntp[0] + 1.0f);
    float N = g_Nsum;
    float cc = (g_avg_cluster[k] + EPSc) / (N + (float)KK * EPSc) * N;
    float4 h = ((const float4*)hdw)[i4];
    float4 w = ((const float4*)g_dw)[i4];
    float4 o;
    o.x = ((h.x * 0.99f + OMD * w.x) / bias) / cc;
    o.y = ((h.y * 0.99f + OMD * w.y) / bias) / cc;
    o.z = ((h.z * 0.99f + OMD * w.z) / bias) / cc;
    o.w = ((h.w * 0.99f + OMD * w.w) / bias) / cc;
    ((float4*)g_codebook_new)[i4] = o;
}

// ---------------------------------------------------------------------------
// 6) gather + loss + indices
// ---------------------------------------------------------------------------
__global__ void vq_gather(const float* __restrict__ X, float* __restrict__ out) {
    int row  = blockIdx.x;              // 16384 blocks x 128 threads
    int lane = threadIdx.x;
    int idx  = (int)(g_best[row] & 0xFFFFFFFFull);

    float4 xv = ((const float4*)(X + (size_t)row * DD))[lane];
    float4 qv = ((const float4*)(g_codebook_new + (size_t)idx * DD))[lane];
    float4 o;
    o.x = xv.x + (qv.x - xv.x);
    o.y = xv.y + (qv.y - xv.y);
    o.z = xv.z + (qv.z - xv.z);
    o.w = xv.w + (qv.w - xv.w);
    ((float4*)out)[row * 128 + lane] = o;

    float dx = xv.x - o.x, dy = xv.y - o.y, dz = xv.z - o.z, dw_ = xv.w - o.w;
    float s = dx * dx + dy * dy + dz * dz + dw_ * dw_;
#pragma unroll
    for (int off = 16; off; off >>= 1) s += __shfl_xor_sync(0xFFFFFFFFu, s, off);
    __shared__ float sred[4];
    if ((lane & 31) == 0) sred[lane >> 5] = s;
    __syncthreads();
    if (lane == 0) {
        float tot = sred[0] + sred[1] + sred[2] + sred[3];
        atomicAdd(out + LOSS_OFF, tot * (0.5f / (float)QELEMS));
        out[IDX_OFF + row] = (float)idx;
    }
}

// ---------------------------------------------------------------------------
extern "C" void kernel_launch(void* const* d_in, const int* in_sizes, int n_in,
                              void* d_out, int out_size) {
    const float* x    = (const float*)d_in[0];   // (8,2048,512)
    const float* cb   = (const float*)d_in[1];   // (4096,512)
    const float* hc   = (const float*)d_in[2];   // (4096,)
    const float* hdw  = (const float*)d_in[3];   // (4096,512)
    const float* cnt  = (const float*)d_in[4];   // scalar
    float* out = (float*)d_out;

    cudaFuncSetAttribute(vq_mma,
                         cudaFuncAttributeMaxDynamicSharedMemorySize, GEMM_SMEM);

    vq_init<<<2048, 256>>>(out);
    vq_sqnorm<<<(KK + RR) / 8, 256>>>(x, cb);
    vq_mma<<<dim3(KK / TN, RR / TM), 256, GEMM_SMEM>>>(x, cb);
    vq_rescue<<<RR, 128>>>(x, cb);
    vq_scatter<<<RR / 2, 256>>>(x);
    vq_stats<<<KK / 256, 256>>>(hc, cnt);
    vq_codebook<<<(KK * DD / 4) / 256, 256>>>(hdw, cnt);
    vq_gather<<<RR, 128>>>(x, out);
}

// round 13
// speedup vs baseline: 2.1772x; 1.6805x over previous
#include <cuda_runtime.h>
#include <cstdint>

#define RR 16384      // B*L rows
#define KK 4096       // clusters
#define DD 512        // feature dim
#define QELEMS (RR * DD)          // 8388608
#define LOSS_OFF QELEMS
#define IDX_OFF  (QELEMS + 1)

// ---- scratch (device globals: no allocation allowed) ----
__device__ float              g_c2[KK];
__device__ float              g_x2[RR];
__device__ unsigned long long g_best[RR];
__device__ int                g_counts[KK];
__device__ float              g_dw[KK * DD];            // 8 MB
__device__ float              g_avg_cluster[KK];
__device__ float              g_codebook_new[KK * DD];  // 8 MB
__device__ float              g_Nsum;
__device__ ulonglong2         g_tb[RR * 128];           // 32 MB: per-row top2 per 32-col group
__device__ int                g_work[RR];
__device__ int                g_nrescue;

// ---------------------------------------------------------------------------
// helpers
// ---------------------------------------------------------------------------
__device__ __forceinline__ uint32_t smem_u32(const void* p) {
    uint32_t a;
    asm("{ .reg .u64 t; cvta.to.shared.u64 t, %1; cvt.u32.u64 %0, t; }"
        : "=r"(a) : "l"(p));
    return a;
}

__device__ __forceinline__ unsigned long long packkey(float d, int k) {
    unsigned int u = __float_as_uint(d);
    u = (u & 0x80000000u) ? ~u : (u | 0x80000000u);   // order-preserving map
    return ((unsigned long long)u << 32) | (unsigned int)k;
}

__device__ __forceinline__ float decf(uint32_t u) {
    uint32_t x = (u & 0x80000000u) ? (u & 0x7FFFFFFFu) : ~u;
    return __uint_as_float(x);
}

// merge two (top1,top2) pairs -> top2 of union
__device__ __forceinline__ void top2merge(unsigned long long& p1, unsigned long long& p2,
                                          unsigned long long q1, unsigned long long q2) {
    unsigned long long n1 = p1 < q1 ? p1 : q1;
    unsigned long long hi = p1 < q1 ? q1 : p1;
    unsigned long long l2 = p2 < q2 ? p2 : q2;
    p1 = n1;
    p2 = hi < l2 ? hi : l2;
}

// ---------------------------------------------------------------------------
// 0) init
// ---------------------------------------------------------------------------
__global__ void vq_init(float* out) {
    int i = blockIdx.x * blockDim.x + threadIdx.x;   // 524288 threads
    ((float4*)g_dw)[i] = make_float4(0.f, 0.f, 0.f, 0.f);
    if (i < KK) g_counts[i] = 0;
    if (i == 0) { g_Nsum = 0.f; g_nrescue = 0; out[LOSS_OFF] = 0.f; }
}

// ---------------------------------------------------------------------------
// 1) squared norms: rows 0..KK-1 -> c2(codebook), rows KK.. -> x2(x)
// ---------------------------------------------------------------------------
__global__ void vq_sqnorm(const float* __restrict__ x, const float* __restrict__ cb) {
    int warp = (blockIdx.x * blockDim.x + threadIdx.x) >> 5;   // 20480 warps
    int lane = threadIdx.x & 31;
    const float* src;
    if (warp < KK) src = cb + (size_t)warp * DD;
    else           src = x + (size_t)(warp - KK) * DD;
    const float4* s4 = (const float4*)src;
    float s = 0.f;
#pragma unroll
    for (int w = 0; w < 4; w++) {
        float4 v = s4[lane + 32 * w];
        s += v.x * v.x + v.y * v.y + v.z * v.z + v.w * v.w;
    }
#pragma unroll
    for (int o = 16; o; o >>= 1) s += __shfl_xor_sync(0xFFFFFFFFu, s, o);
    if (lane == 0) {
        if (warp < KK) g_c2[warp] = s;
        else           g_x2[warp - KK] = s;
    }
}

// ---------------------------------------------------------------------------
// 2) tf32 HMMA GEMM (mma.sync m16n8k8) + fused per-row top-2 per 32-col group
//    CTA tile 128x256, 8 warps of 64x64, K staged 32 wide, cp.async 3-buffer
// ---------------------------------------------------------------------------
#define TM 128
#define TN 256
#define TKS 32
#define NST (DD / TKS)           // 16
#define NBUF 3
#define APAD 36                  // row stride in floats (conflict-free)
#define A_FLOATS (TM * APAD)     // 4608
#define B_FLOATS (TN * APAD)     // 9216
#define SM_A 1024
#define SM_B (SM_A + NBUF * A_FLOATS * 4)        // 56320
#define GEMM_SMEM (SM_B + NBUF * B_FLOATS * 4)   // 166912

__device__ __forceinline__ void stage_load(const float* __restrict__ X,
                                           const float* __restrict__ C,
                                           uint32_t sA, uint32_t sB,
                                           int row0, int col0, int kt, int t) {
#pragma unroll
    for (int i = 0; i < 4; i++) {           // A: 128 rows x 32 k = 1024 16B chunks
        int ch = t + i * 256;
        int r = ch >> 3, c4 = (ch & 7) * 4;
        uint32_t dst = sA + (uint32_t)(r * APAD + c4) * 4u;
        const float* src = X + (size_t)(row0 + r) * DD + kt + c4;
        asm volatile("cp.async.cg.shared.global [%0], [%1], 16;"
                     :: "r"(dst), "l"(src) : "memory");
    }
#pragma unroll
    for (int i = 0; i < 8; i++) {           // B: 256 rows x 32 k = 2048 chunks
        int ch = t + i * 256;
        int r = ch >> 3, c4 = (ch & 7) * 4;
        uint32_t dst = sB + (uint32_t)(r * APAD + c4) * 4u;
        const float* src = C + (size_t)(col0 + r) * DD + kt + c4;
        asm volatile("cp.async.cg.shared.global [%0], [%1], 16;"
                     :: "r"(dst), "l"(src) : "memory");
    }
}

__global__ __launch_bounds__(256, 1)
void vq_mma(const float* __restrict__ X, const float* __restrict__ C) {
    extern __shared__ char sm[];
    float* c2s = (float*)sm;                 // [256]
    const uint32_t smb = smem_u32(sm);
    const int t = threadIdx.x, lane = t & 31, warp = t >> 5;
    const int wm = warp >> 2, wn = warp & 3;
    const int row0 = blockIdx.y * TM, col0 = blockIdx.x * TN;

    c2s[t] = g_c2[col0 + t];

    float acc[4][8][4];
#pragma unroll
    for (int a = 0; a < 4; a++)
#pragma unroll
        for (int b = 0; b < 8; b++)
#pragma unroll
            for (int c = 0; c < 4; c++) acc[a][b][c] = 0.f;

    // prefetch stages 0 and 1
    stage_load(X, C, smb + SM_A, smb + SM_B, row0, col0, 0, t);
    asm volatile("cp.async.commit_group;" ::: "memory");
    stage_load(X, C, smb + SM_A + (uint32_t)(A_FLOATS * 4),
               smb + SM_B + (uint32_t)(B_FLOATS * 4), row0, col0, TKS, t);
    asm volatile("cp.async.commit_group;" ::: "memory");

    for (int s = 0; s < NST; s++) {
        asm volatile("cp.async.wait_group 1;" ::: "memory");   // stage s resident
        __syncthreads();   // all warps done with stage s-1 -> its buffer reusable

        if (s + 2 < NST) {
            const int nb = (s + 2) % NBUF;
            stage_load(X, C,
                       smb + SM_A + (uint32_t)(nb * A_FLOATS * 4),
                       smb + SM_B + (uint32_t)(nb * B_FLOATS * 4),
                       row0, col0, (s + 2) * TKS, t);
        }
        asm volatile("cp.async.commit_group;" ::: "memory");

        const int cb_ = s % NBUF;
        const float* As_s = (const float*)(sm + SM_A + cb_ * A_FLOATS * 4);
        const float* Bs_s = (const float*)(sm + SM_B + cb_ * B_FLOATS * 4);

#pragma unroll
        for (int ks = 0; ks < 4; ks++) {
            const int k8 = ks * 8;
            uint32_t a0[4], a1[4], a2[4], a3[4], b0[8], b1[8];
#pragma unroll
            for (int mf = 0; mf < 4; mf++) {
                const float* p = As_s + (wm * 64 + mf * 16 + (lane >> 2)) * APAD
                               + k8 + (lane & 3);
                a0[mf] = __float_as_uint(p[0]);
                a2[mf] = __float_as_uint(p[4]);
                a1[mf] = __float_as_uint(p[8 * APAD]);
                a3[mf] = __float_as_uint(p[8 * APAD + 4]);
            }
#pragma unroll
            for (int nf = 0; nf < 8; nf++) {
                const float* p = Bs_s + (wn * 64 + nf * 8 + (lane >> 2)) * APAD
                               + k8 + (lane & 3);
                b0[nf] = __float_as_uint(p[0]);
                b1[nf] = __float_as_uint(p[4]);
            }
#pragma unroll
            for (int mf = 0; mf < 4; mf++)
#pragma unroll
                for (int nf = 0; nf < 8; nf++)
                    asm volatile(
                        "mma.sync.aligned.m16n8k8.row.col.f32.tf32.tf32.f32 "
                        "{%0,%1,%2,%3}, {%4,%5,%6,%7}, {%8,%9}, {%0,%1,%2,%3};"
                        : "+f"(acc[mf][nf][0]), "+f"(acc[mf][nf][1]),
                          "+f"(acc[mf][nf][2]), "+f"(acc[mf][nf][3])
                        : "r"(a0[mf]), "r"(a1[mf]), "r"(a2[mf]), "r"(a3[mf]),
                          "r"(b0[nf]), "r"(b1[nf]));
        }
    }

    // epilogue: per-row top-2 within each 32-col group (2 groups per warp tile)
    // acc frag val v: row = rs*8 + lane>>2 (rs = v>>1), col = (lane&3)*2 + (v&1)
#pragma unroll
    for (int mf = 0; mf < 4; mf++) {
#pragma unroll
        for (int rs = 0; rs < 2; rs++) {
#pragma unroll
            for (int h = 0; h < 2; h++) {       // 32-col half of the 64-col warp tile
                unsigned long long p1 = ~0ull, p2 = ~0ull;
#pragma unroll
                for (int nf = h * 4; nf < h * 4 + 4; nf++) {
#pragma unroll
                    for (int j = 0; j < 2; j++) {
                        int lc = wn * 64 + nf * 8 + (lane & 3) * 2 + j;
                        float d = c2s[lc] - 2.0f * acc[mf][nf][rs * 2 + j];
                        unsigned long long key = packkey(d, col0 + lc);
                        if (key < p1) { p2 = p1; p1 = key; }
                        else if (key < p2) p2 = key;
                    }
                }
#pragma unroll
                for (int off = 1; off <= 2; off <<= 1) {
                    unsigned long long q1 = __shfl_xor_sync(0xFFFFFFFFu, p1, off);
                    unsigned long long q2 = __shfl_xor_sync(0xFFFFFFFFu, p2, off);
                    top2merge(p1, p2, q1, q2);
                }
                if ((lane & 3) == 0) {
                    int row = row0 + wm * 64 + mf * 16 + rs * 8 + (lane >> 2);
                    g_tb[row * 128 + blockIdx.x * 8 + wn * 2 + h] =
                        make_ulonglong2(p1, p2);
                }
            }
        }
    }
}

// ---------------------------------------------------------------------------
// 2b) gate: warp per row — commit approx argmin if gap >= TAU, else enqueue
// ---------------------------------------------------------------------------
#define TAU 0.025f

__global__ void vq_gate() {
    int row  = (blockIdx.x * blockDim.x + threadIdx.x) >> 5;   // 16384 warps
    int lane = threadIdx.x & 31;
    const ulonglong2* tb = g_tb + (size_t)row * 128;

    unsigned long long p1 = ~0ull, p2 = ~0ull;
#pragma unroll
    for (int i = 0; i < 4; i++) {
        ulonglong2 e = tb[lane + 32 * i];
        unsigned long long lo = e.x < e.y ? e.x : e.y;
        unsigned long long hi = e.x < e.y ? e.y : e.x;
        top2merge(p1, p2, lo, hi);
    }
#pragma unroll
    for (int off = 16; off; off >>= 1) {
        unsigned long long q1 = __shfl_xor_sync(0xFFFFFFFFu, p1, off);
        unsigned long long q2 = __shfl_xor_sync(0xFFFFFFFFu, p2, off);
        top2merge(p1, p2, q1, q2);
    }
    if (lane == 0) {
        float gap = decf((uint32_t)(p2 >> 32)) - decf((uint32_t)(p1 >> 32));
        if (gap >= TAU) {
            g_best[row] = p1;           // approx argmin provably exact
        } else {
            int w = atomicAdd(&g_nrescue, 1);
            g_work[w] = row;
        }
    }
}

// ---------------------------------------------------------------------------
// 2c) rescue: exact fp32 rescore of 256 candidates, flagged rows only
//     exact shape matches reference: (x2 - 2*dot) + c2
// ---------------------------------------------------------------------------
__global__ void vq_rescue2(const float* __restrict__ X, const float* __restrict__ C) {
    __shared__ float xs[DD];
    __shared__ unsigned long long red[128];
    const int t = threadIdx.x;
    const int n = g_nrescue;            // stable: gate kernel completed

    for (int i = blockIdx.x; i < n; i += gridDim.x) {
        const int row = g_work[i];
        ((float4*)xs)[t] = ((const float4*)X)[row * 128 + t];
        ulonglong2 mine = g_tb[(size_t)row * 128 + t];
        __syncthreads();

        const float x2r = g_x2[row];
        unsigned long long best = ~0ull;
        const float4* x4 = (const float4*)xs;
#pragma unroll
        for (int cidx = 0; cidx < 2; cidx++) {
            int k = (int)((cidx ? mine.y : mine.x) & 0xFFFFFFFFu);
            const float4* c4 = (const float4*)(C + (size_t)k * DD);
            float d0 = 0.f, d1 = 0.f, d2 = 0.f, d3 = 0.f;
#pragma unroll 8
            for (int j = 0; j < 128; j++) {
                float4 a = x4[j], b = c4[j];
                d0 = fmaf(a.x, b.x, d0); d1 = fmaf(a.y, b.y, d1);
                d2 = fmaf(a.z, b.z, d2); d3 = fmaf(a.w, b.w, d3);
            }
            float dot = (d0 + d1) + (d2 + d3);
            unsigned long long key = packkey((x2r - 2.0f * dot) + g_c2[k], k);
            if (key < best) best = key;
        }
        red[t] = best;
        __syncthreads();
        for (int s = 64; s; s >>= 1) {
            if (t < s) red[t] = red[t] < red[t + s] ? red[t] : red[t + s];
            __syncthreads();
        }
        if (t == 0) g_best[row] = red[0];
        __syncthreads();
    }
}

// ---------------------------------------------------------------------------
// 3) scatter: counts + dw
// ---------------------------------------------------------------------------
__global__ void vq_scatter(const float* __restrict__ X) {
    int row  = blockIdx.x * 2 + (threadIdx.x >> 7);
    int lane = threadIdx.x & 127;
    int idx  = (int)(g_best[row] & 0xFFFFFFFFull);
    if (lane == 0) atomicAdd(&g_counts[idx], 1);
    float4 v = ((const float4*)(X + (size_t)row * DD))[lane];
    float* dst = g_dw + (size_t)idx * DD + lane * 4;
    atomicAdd(dst + 0, v.x);
    atomicAdd(dst + 1, v.y);
    atomicAdd(dst + 2, v.z);
    atomicAdd(dst + 3, v.w);
}

// ---------------------------------------------------------------------------
// 4) per-cluster EMA stats: avg_cluster + Nsum
// ---------------------------------------------------------------------------
__global__ void vq_stats(const float* __restrict__ hc, const float* __restrict__ cntp) {
    const float OMD = 1.0f - 0.99f;
    int k = blockIdx.x * 256 + threadIdx.x;
    float bias = 1.0f - powf(0.99f, cntp[0] + 1.0f);
    float avg = (hc[k] * 0.99f + OMD * (float)g_counts[k]) / bias;
    g_avg_cluster[k] = avg;

    float s = avg;
#pragma unroll
    for (int o = 16; o; o >>= 1) s += __shfl_xor_sync(0xFFFFFFFFu, s, o);
    __shared__ float sred[8];
    if ((threadIdx.x & 31) == 0) sred[threadIdx.x >> 5] = s;
    __syncthreads();
    if (threadIdx.x == 0) {
        float tot = 0.f;
#pragma unroll
        for (int w = 0; w < 8; w++) tot += sred[w];
        atomicAdd(&g_Nsum, tot);
    }
}

// ---------------------------------------------------------------------------
// 5) codebook_new
// ---------------------------------------------------------------------------
__global__ void vq_codebook(const float* __restrict__ hdw, const float* __restrict__ cntp) {
    const float OMD = 1.0f - 0.99f;
    const float EPSc = 1e-5f;
    int i4 = blockIdx.x * blockDim.x + threadIdx.x;   // 524288 float4s
    int k = i4 >> 7;
    float bias = 1.0f - powf(0.99f, cntp[0] + 1.0f);
    float N = g_Nsum;
    float cc = (g_avg_cluster[k] + EPSc) / (N + (float)KK * EPSc) * N;
    float4 h = ((const float4*)hdw)[i4];
    float4 w = ((const float4*)g_dw)[i4];
    float4 o;
    o.x = ((h.x * 0.99f + OMD * w.x) / bias) / cc;
    o.y = ((h.y * 0.99f + OMD * w.y) / bias) / cc;
    o.z = ((h.z * 0.99f + OMD * w.z) / bias) / cc;
    o.w = ((h.w * 0.99f + OMD * w.w) / bias) / cc;
    ((float4*)g_codebook_new)[i4] = o;
}

// ---------------------------------------------------------------------------
// 6) gather + loss + indices
// ---------------------------------------------------------------------------
__global__ void vq_gather(const float* __restrict__ X, float* __restrict__ out) {
    int row  = blockIdx.x;              // 16384 blocks x 128 threads
    int lane = threadIdx.x;
    int idx  = (int)(g_best[row] & 0xFFFFFFFFull);

    float4 xv = ((const float4*)(X + (size_t)row * DD))[lane];
    float4 qv = ((const float4*)(g_codebook_new + (size_t)idx * DD))[lane];
    float4 o;
    o.x = xv.x + (qv.x - xv.x);
    o.y = xv.y + (qv.y - xv.y);
    o.z = xv.z + (qv.z - xv.z);
    o.w = xv.w + (qv.w - xv.w);
    ((float4*)out)[row * 128 + lane] = o;

    float dx = xv.x - o.x, dy = xv.y - o.y, dz = xv.z - o.z, dw_ = xv.w - o.w;
    float s = dx * dx + dy * dy + dz * dz + dw_ * dw_;
#pragma unroll
    for (int off = 16; off; off >>= 1) s += __shfl_xor_sync(0xFFFFFFFFu, s, off);
    __shared__ float sred[4];
    if ((lane & 31) == 0) sred[lane >> 5] = s;
    __syncthreads();
    if (lane == 0) {
        float tot = sred[0] + sred[1] + sred[2] + sred[3];
        atomicAdd(out + LOSS_OFF, tot * (0.5f / (float)QELEMS));
        out[IDX_OFF + row] = (float)idx;
    }
}

// ---------------------------------------------------------------------------
extern "C" void kernel_launch(void* const* d_in, const int* in_sizes, int n_in,
                              void* d_out, int out_size) {
    const float* x    = (const float*)d_in[0];   // (8,2048,512)
    const float* cb   = (const float*)d_in[1];   // (4096,512)
    const float* hc   = (const float*)d_in[2];   // (4096,)
    const float* hdw  = (const float*)d_in[3];   // (4096,512)
    const float* cnt  = (const float*)d_in[4];   // scalar
    float* out = (float*)d_out;

    cudaFuncSetAttribute(vq_mma,
                         cudaFuncAttributeMaxDynamicSharedMemorySize, GEMM_SMEM);

    vq_init<<<2048, 256>>>(out);
    vq_sqnorm<<<(KK + RR) / 8, 256>>>(x, cb);
    vq_mma<<<dim3(KK / TN, RR / TM), 256, GEMM_SMEM>>>(x, cb);
    vq_gate<<<RR / 4, 128>>>();
    vq_rescue2<<<1024, 128>>>(x, cb);
    vq_scatter<<<RR / 2, 256>>>(x);
    vq_stats<<<KK / 256, 256>>>(hc, cnt);
    vq_codebook<<<(KK * DD / 4) / 256, 256>>>(hdw, cnt);
    vq_gather<<<RR, 128>>>(x, out);
}

// round 14
// speedup vs baseline: 2.2106x; 1.0154x over previous
#include <cuda_runtime.h>
#include <cstdint>

#define RR 16384      // B*L rows
#define KK 4096       // clusters
#define DD 512        // feature dim
#define QELEMS (RR * DD)          // 8388608
#define LOSS_OFF QELEMS
#define IDX_OFF  (QELEMS + 1)

// ---- scratch (device globals: no allocation allowed) ----
__device__ float              g_c2[KK];
__device__ float              g_x2[RR];
__device__ unsigned long long g_best[RR];
__device__ int                g_counts[KK];
__device__ float              g_dw[KK * DD];            // 8 MB
__device__ float              g_avg_cluster[KK];
__device__ float              g_codebook_new[KK * DD];  // 8 MB
__device__ float              g_Nsum;
__device__ ulonglong2         g_tb[RR * 128];           // 32 MB: per-row top2 per 32-col group
__device__ int                g_work[RR];
__device__ int                g_nrescue;

// ---------------------------------------------------------------------------
// helpers
// ---------------------------------------------------------------------------
__device__ __forceinline__ uint32_t smem_u32(const void* p) {
    uint32_t a;
    asm("{ .reg .u64 t; cvta.to.shared.u64 t, %1; cvt.u32.u64 %0, t; }"
        : "=r"(a) : "l"(p));
    return a;
}

__device__ __forceinline__ unsigned long long packkey(float d, int k) {
    unsigned int u = __float_as_uint(d);
    u = (u & 0x80000000u) ? ~u : (u | 0x80000000u);   // order-preserving map
    return ((unsigned long long)u << 32) | (unsigned int)k;
}

__device__ __forceinline__ float decf(uint32_t u) {
    uint32_t x = (u & 0x80000000u) ? (u & 0x7FFFFFFFu) : ~u;
    return __uint_as_float(x);
}

// merge two (top1,top2) pairs -> top2 of union
__device__ __forceinline__ void top2merge(unsigned long long& p1, unsigned long long& p2,
                                          unsigned long long q1, unsigned long long q2) {
    unsigned long long n1 = p1 < q1 ? p1 : q1;
    unsigned long long hi = p1 < q1 ? q1 : p1;
    unsigned long long l2 = p2 < q2 ? p2 : q2;
    p1 = n1;
    p2 = hi < l2 ? hi : l2;
}

// ---------------------------------------------------------------------------
// 0) init
// ---------------------------------------------------------------------------
__global__ void vq_init(float* out) {
    int i = blockIdx.x * blockDim.x + threadIdx.x;   // 524288 threads
    ((float4*)g_dw)[i] = make_float4(0.f, 0.f, 0.f, 0.f);
    if (i < KK) g_counts[i] = 0;
    if (i == 0) { g_Nsum = 0.f; g_nrescue = 0; out[LOSS_OFF] = 0.f; }
}

// ---------------------------------------------------------------------------
// 1) squared norms: rows 0..KK-1 -> c2(codebook), rows KK.. -> x2(x)
// ---------------------------------------------------------------------------
__global__ void vq_sqnorm(const float* __restrict__ x, const float* __restrict__ cb) {
    int warp = (blockIdx.x * blockDim.x + threadIdx.x) >> 5;   // 20480 warps
    int lane = threadIdx.x & 31;
    const float* src;
    if (warp < KK) src = cb + (size_t)warp * DD;
    else           src = x + (size_t)(warp - KK) * DD;
    const float4* s4 = (const float4*)src;
    float s = 0.f;
#pragma unroll
    for (int w = 0; w < 4; w++) {
        float4 v = s4[lane + 32 * w];
        s += v.x * v.x + v.y * v.y + v.z * v.z + v.w * v.w;
    }
#pragma unroll
    for (int o = 16; o; o >>= 1) s += __shfl_xor_sync(0xFFFFFFFFu, s, o);
    if (lane == 0) {
        if (warp < KK) g_c2[warp] = s;
        else           g_x2[warp - KK] = s;
    }
}

// ---------------------------------------------------------------------------
// 2) tf32 HMMA GEMM (mma.sync m16n8k8) + fused per-row top-2 per 32-col group
//    CTA tile 128x256, 8 warps of 64x64, K staged 32 wide, cp.async 4-buffer,
//    ldmatrix fragment loads
// ---------------------------------------------------------------------------
#define TM 128
#define TN 256
#define TKS 32
#define NST (DD / TKS)           // 16
#define NBUF 4
#define APAD 36                  // row stride in floats (conflict-free; LDSM phases too)
#define A_FLOATS (TM * APAD)     // 4608
#define B_FLOATS (TN * APAD)     // 9216
#define SM_A 1024
#define SM_B (SM_A + NBUF * A_FLOATS * 4)        // 74752
#define GEMM_SMEM (SM_B + NBUF * B_FLOATS * 4)   // 222208

__device__ __forceinline__ void stage_load(const float* __restrict__ X,
                                           const float* __restrict__ C,
                                           uint32_t sA, uint32_t sB,
                                           int row0, int col0, int kt, int t) {
#pragma unroll
    for (int i = 0; i < 4; i++) {           // A: 128 rows x 32 k = 1024 16B chunks
        int ch = t + i * 256;
        int r = ch >> 3, c4 = (ch & 7) * 4;
        uint32_t dst = sA + (uint32_t)(r * APAD + c4) * 4u;
        const float* src = X + (size_t)(row0 + r) * DD + kt + c4;
        asm volatile("cp.async.cg.shared.global [%0], [%1], 16;"
                     :: "r"(dst), "l"(src) : "memory");
    }
#pragma unroll
    for (int i = 0; i < 8; i++) {           // B: 256 rows x 32 k = 2048 chunks
        int ch = t + i * 256;
        int r = ch >> 3, c4 = (ch & 7) * 4;
        uint32_t dst = sB + (uint32_t)(r * APAD + c4) * 4u;
        const float* src = C + (size_t)(col0 + r) * DD + kt + c4;
        asm volatile("cp.async.cg.shared.global [%0], [%1], 16;"
                     :: "r"(dst), "l"(src) : "memory");
    }
}

__global__ __launch_bounds__(256, 1)
void vq_mma(const float* __restrict__ X, const float* __restrict__ C) {
    extern __shared__ char sm[];
    float* c2s = (float*)sm;                 // [256]
    const uint32_t smb = smem_u32(sm);
    const int t = threadIdx.x, lane = t & 31, warp = t >> 5;
    const int wm = warp >> 2, wn = warp & 3;
    const int row0 = blockIdx.y * TM, col0 = blockIdx.x * TN;

    c2s[t] = g_c2[col0 + t];

    float acc[4][8][4];
#pragma unroll
    for (int a = 0; a < 4; a++)
#pragma unroll
        for (int b = 0; b < 8; b++)
#pragma unroll
            for (int c = 0; c < 4; c++) acc[a][b][c] = 0.f;

    // ldmatrix base addresses (buffer 0, k8 = 0)
    // A x4: matrices (r,k),(r+8,k),(r,k+4),(r+8,k+4); lane seg picks matrix row source
    const int aseg = lane >> 3;                       // 0..3
    const int arow = (aseg & 1) * 8 + (lane & 7);     // row-within-16
    const int akof = (aseg >> 1) * 4;                 // k offset 0 or 4
    uint32_t aBase[4];
#pragma unroll
    for (int mf = 0; mf < 4; mf++)
        aBase[mf] = smb + SM_A +
            (uint32_t)((wm * 64 + mf * 16 + arow) * APAD + akof) * 4u;
    // B x2: matrix0 = 8 n-rows @ k..k+3 (lanes 0-7), matrix1 same rows @ k+4 (lanes 8-15)
    const int bl  = lane & 15;
    const int bn  = bl & 7;
    const int bkf = (bl >> 3) * 4;
    uint32_t bBase[8];
#pragma unroll
    for (int nf = 0; nf < 8; nf++)
        bBase[nf] = smb + SM_B +
            (uint32_t)((wn * 64 + nf * 8 + bn) * APAD + bkf) * 4u;

    // prefetch stages 0..2
#pragma unroll
    for (int p = 0; p < 3; p++) {
        stage_load(X, C, smb + SM_A + (uint32_t)(p * A_FLOATS * 4),
                   smb + SM_B + (uint32_t)(p * B_FLOATS * 4), row0, col0, p * TKS, t);
        asm volatile("cp.async.commit_group;" ::: "memory");
    }

    for (int s = 0; s < NST; s++) {
        asm volatile("cp.async.wait_group 2;" ::: "memory");   // stage s resident
        __syncthreads();   // all warps done with stage s-1 -> its buffer reusable

        if (s + 3 < NST) {
            const int nb = (s + 3) & (NBUF - 1);
            stage_load(X, C,
                       smb + SM_A + (uint32_t)(nb * A_FLOATS * 4),
                       smb + SM_B + (uint32_t)(nb * B_FLOATS * 4),
                       row0, col0, (s + 3) * TKS, t);
        }
        asm volatile("cp.async.commit_group;" ::: "memory");

        const uint32_t offA = (uint32_t)((s & (NBUF - 1)) * A_FLOATS * 4);
        const uint32_t offB = (uint32_t)((s & (NBUF - 1)) * B_FLOATS * 4);

#pragma unroll
        for (int ks = 0; ks < 4; ks++) {
            const uint32_t k8b = (uint32_t)(ks * 8 * 4);
            uint32_t a0[4], a1[4], a2[4], a3[4], b0[8], b1[8];
#pragma unroll
            for (int mf = 0; mf < 4; mf++)
                asm volatile(
                    "ldmatrix.sync.aligned.m8n8.x4.shared.b16 {%0,%1,%2,%3}, [%4];"
                    : "=r"(a0[mf]), "=r"(a1[mf]), "=r"(a2[mf]), "=r"(a3[mf])
                    : "r"(aBase[mf] + offA + k8b));
#pragma unroll
            for (int nf = 0; nf < 8; nf++)
                asm volatile(
                    "ldmatrix.sync.aligned.m8n8.x2.shared.b16 {%0,%1}, [%2];"
                    : "=r"(b0[nf]), "=r"(b1[nf])
                    : "r"(bBase[nf] + offB + k8b));
#pragma unroll
            for (int mf = 0; mf < 4; mf++)
#pragma unroll
                for (int nf = 0; nf < 8; nf++)
                    asm volatile(
                        "mma.sync.aligned.m16n8k8.row.col.f32.tf32.tf32.f32 "
                        "{%0,%1,%2,%3}, {%4,%5,%6,%7}, {%8,%9}, {%0,%1,%2,%3};"
                        : "+f"(acc[mf][nf][0]), "+f"(acc[mf][nf][1]),
                          "+f"(acc[mf][nf][2]), "+f"(acc[mf][nf][3])
                        : "r"(a0[mf]), "r"(a1[mf]), "r"(a2[mf]), "r"(a3[mf]),
                          "r"(b0[nf]), "r"(b1[nf]));
        }
    }

    // epilogue: per-row top-2 within each 32-col group (2 groups per warp tile)
    // acc frag val v: row = rs*8 + lane>>2 (rs = v>>1), col = (lane&3)*2 + (v&1)
#pragma unroll
    for (int mf = 0; mf < 4; mf++) {
#pragma unroll
        for (int rs = 0; rs < 2; rs++) {
#pragma unroll
            for (int h = 0; h < 2; h++) {       // 32-col half of the 64-col warp tile
                unsigned long long p1 = ~0ull, p2 = ~0ull;
#pragma unroll
                for (int nf = h * 4; nf < h * 4 + 4; nf++) {
#pragma unroll
                    for (int j = 0; j < 2; j++) {
                        int lc = wn * 64 + nf * 8 + (lane & 3) * 2 + j;
                        float d = c2s[lc] - 2.0f * acc[mf][nf][rs * 2 + j];
                        unsigned long long key = packkey(d, col0 + lc);
                        if (key < p1) { p2 = p1; p1 = key; }
                        else if (key < p2) p2 = key;
                    }
                }
#pragma unroll
                for (int off = 1; off <= 2; off <<= 1) {
                    unsigned long long q1 = __shfl_xor_sync(0xFFFFFFFFu, p1, off);
                    unsigned long long q2 = __shfl_xor_sync(0xFFFFFFFFu, p2, off);
                    top2merge(p1, p2, q1, q2);
                }
                if ((lane & 3) == 0) {
                    int row = row0 + wm * 64 + mf * 16 + rs * 8 + (lane >> 2);
                    g_tb[row * 128 + blockIdx.x * 8 + wn * 2 + h] =
                        make_ulonglong2(p1, p2);
                }
            }
        }
    }
}

// ---------------------------------------------------------------------------
// 2b) gate: warp per row — commit approx argmin if gap >= TAU, else enqueue
// ---------------------------------------------------------------------------
#define TAU 0.025f

__global__ void vq_gate() {
    int row  = (blockIdx.x * blockDim.x + threadIdx.x) >> 5;   // 16384 warps
    int lane = threadIdx.x & 31;
    const ulonglong2* tb = g_tb + (size_t)row * 128;

    unsigned long long p1 = ~0ull, p2 = ~0ull;
#pragma unroll
    for (int i = 0; i < 4; i++) {
        ulonglong2 e = tb[lane + 32 * i];
        unsigned long long lo = e.x < e.y ? e.x : e.y;
        unsigned long long hi = e.x < e.y ? e.y : e.x;
        top2merge(p1, p2, lo, hi);
    }
#pragma unroll
    for (int off = 16; off; off >>= 1) {
        unsigned long long q1 = __shfl_xor_sync(0xFFFFFFFFu, p1, off);
        unsigned long long q2 = __shfl_xor_sync(0xFFFFFFFFu, p2, off);
        top2merge(p1, p2, q1, q2);
    }
    if (lane == 0) {
        float gap = decf((uint32_t)(p2 >> 32)) - decf((uint32_t)(p1 >> 32));
        if (gap >= TAU) {
            g_best[row] = p1;           // approx argmin provably exact
        } else {
            int w = atomicAdd(&g_nrescue, 1);
            g_work[w] = row;
        }
    }
}

// ---------------------------------------------------------------------------
// 2c) rescue: exact fp32 rescore of 256 candidates, flagged rows only
//     exact shape matches reference: (x2 - 2*dot) + c2
// ---------------------------------------------------------------------------
__global__ void vq_rescue2(const float* __restrict__ X, const float* __restrict__ C) {
    __shared__ float xs[DD];
    __shared__ unsigned long long red[128];
    const int t = threadIdx.x;
    const int n = g_nrescue;            // stable: gate kernel completed

    for (int i = blockIdx.x; i < n; i += gridDim.x) {
        const int row = g_work[i];
        ((float4*)xs)[t] = ((const float4*)X)[row * 128 + t];
        ulonglong2 mine = g_tb[(size_t)row * 128 + t];
        __syncthreads();

        const float x2r = g_x2[row];
        unsigned long long best = ~0ull;
        const float4* x4 = (const float4*)xs;
#pragma unroll
        for (int cidx = 0; cidx < 2; cidx++) {
            int k = (int)((cidx ? mine.y : mine.x) & 0xFFFFFFFFu);
            const float4* c4 = (const float4*)(C + (size_t)k * DD);
            float d0 = 0.f, d1 = 0.f, d2 = 0.f, d3 = 0.f;
#pragma unroll 8
            for (int j = 0; j < 128; j++) {
                float4 a = x4[j], b = c4[j];
                d0 = fmaf(a.x, b.x, d0); d1 = fmaf(a.y, b.y, d1);
                d2 = fmaf(a.z, b.z, d2); d3 = fmaf(a.w, b.w, d3);
            }
            float dot = (d0 + d1) + (d2 + d3);
            unsigned long long key = packkey((x2r - 2.0f * dot) + g_c2[k], k);
            if (key < best) best = key;
        }
        red[t] = best;
        __syncthreads();
        for (int s = 64; s; s >>= 1) {
            if (t < s) red[t] = red[t] < red[t + s] ? red[t] : red[t + s];
            __syncthreads();
        }
        if (t == 0) g_best[row] = red[0];
        __syncthreads();
    }
}

// ---------------------------------------------------------------------------
// 3) scatter: counts + dw
// ---------------------------------------------------------------------------
__global__ void vq_scatter(const float* __restrict__ X) {
    int row  = blockIdx.x * 2 + (threadIdx.x >> 7);
    int lane = threadIdx.x & 127;
    int idx  = (int)(g_best[row] & 0xFFFFFFFFull);
    if (lane == 0) atomicAdd(&g_counts[idx], 1);
    float4 v = ((const float4*)(X + (size_t)row * DD))[lane];
    float* dst = g_dw + (size_t)idx * DD + lane * 4;
    atomicAdd(dst + 0, v.x);
    atomicAdd(dst + 1, v.y);
    atomicAdd(dst + 2, v.z);
    atomicAdd(dst + 3, v.w);
}

// ---------------------------------------------------------------------------
// 4) per-cluster EMA stats: avg_cluster + Nsum
// ---------------------------------------------------------------------------
__global__ void vq_stats(const float* __restrict__ hc, const float* __restrict__ cntp) {
    const float OMD = 1.0f - 0.99f;
    int k = blockIdx.x * 256 + threadIdx.x;
    float bias = 1.0f - powf(0.99f, cntp[0] + 1.0f);
    float avg = (hc[k] * 0.99f + OMD * (float)g_counts[k]) / bias;
    g_avg_cluster[k] = avg;

    float s = avg;
#pragma unroll
    for (int o = 16; o; o >>= 1) s += __shfl_xor_sync(0xFFFFFFFFu, s, o);
    __shared__ float sred[8];
    if ((threadIdx.x & 31) == 0) sred[threadIdx.x >> 5] = s;
    __syncthreads();
    if (threadIdx.x == 0) {
        float tot = 0.f;
#pragma unroll
        for (int w = 0; w < 8; w++) tot += sred[w];
        atomicAdd(&g_Nsum, tot);
    }
}

// ---------------------------------------------------------------------------
// 5) codebook_new
// ---------------------------------------------------------------------------
__global__ void vq_codebook(const float* __restrict__ hdw, const float* __restrict__ cntp) {
    const float OMD = 1.0f - 0.99f;
    const float EPSc = 1e-5f;
    int i4 = blockIdx.x * blockDim.x + threadIdx.x;   // 524288 float4s
    int k = i4 >> 7;
    float bias = 1.0f - powf(0.99f, cntp[0] + 1.0f);
    float N = g_Nsum;
    float cc = (g_avg_cluster[k] + EPSc) / (N + (float)KK * EPSc) * N;
    float4 h = ((const float4*)hdw)[i4];
    float4 w = ((const float4*)g_dw)[i4];
    float4 o;
    o.x = ((h.x * 0.99f + OMD * w.x) / bias) / cc;
    o.y = ((h.y * 0.99f + OMD * w.y) / bias) / cc;
    o.z = ((h.z * 0.99f + OMD * w.z) / bias) / cc;
    o.w = ((h.w * 0.99f + OMD * w.w) / bias) / cc;
    ((float4*)g_codebook_new)[i4] = o;
}

// ---------------------------------------------------------------------------
// 6) gather + loss + indices
// ---------------------------------------------------------------------------
__global__ void vq_gather(const float* __restrict__ X, float* __restrict__ out) {
    int row  = blockIdx.x;              // 16384 blocks x 128 threads
    int lane = threadIdx.x;
    int idx  = (int)(g_best[row] & 0xFFFFFFFFull);

    float4 xv = ((const float4*)(X + (size_t)row * DD))[lane];
    float4 qv = ((const float4*)(g_codebook_new + (size_t)idx * DD))[lane];
    float4 o;
    o.x = xv.x + (qv.x - xv.x);
    o.y = xv.y + (qv.y - xv.y);
    o.z = xv.z + (qv.z - xv.z);
    o.w = xv.w + (qv.w - xv.w);
    ((float4*)out)[row * 128 + lane] = o;

    float dx = xv.x - o.x, dy = xv.y - o.y, dz = xv.z - o.z, dw_ = xv.w - o.w;
    float s = dx * dx + dy * dy + dz * dz + dw_ * dw_;
#pragma unroll
    for (int off = 16; off; off >>= 1) s += __shfl_xor_sync(0xFFFFFFFFu, s, off);
    __shared__ float sred[4];
    if ((lane & 31) == 0) sred[lane >> 5] = s;
    __syncthreads();
    if (lane == 0) {
        float tot = sred[0] + sred[1] + sred[2] + sred[3];
        atomicAdd(out + LOSS_OFF, tot * (0.5f / (float)QELEMS));
        out[IDX_OFF + row] = (float)idx;
    }
}

// ---------------------------------------------------------------------------
extern "C" void kernel_launch(void* const* d_in, const int* in_sizes, int n_in,
                              void* d_out, int out_size) {
    const float* x    = (const float*)d_in[0];   // (8,2048,512)
    const float* cb   = (const float*)d_in[1];   // (4096,512)
    const float* hc   = (const float*)d_in[2];   // (4096,)
    const float* hdw  = (const float*)d_in[3];   // (4096,512)
    const float* cnt  = (const float*)d_in[4];   // scalar
    float* out = (float*)d_out;

    cudaFuncSetAttribute(vq_mma,
                         cudaFuncAttributeMaxDynamicSharedMemorySize, GEMM_SMEM);

    vq_init<<<2048, 256>>>(out);
    vq_sqnorm<<<(KK + RR) / 8, 256>>>(x, cb);
    vq_mma<<<dim3(KK / TN, RR / TM), 256, GEMM_SMEM>>>(x, cb);
    vq_gate<<<RR / 4, 128>>>();
    vq_rescue2<<<1024, 128>>>(x, cb);
    vq_scatter<<<RR / 2, 256>>>(x);
    vq_stats<<<KK / 256, 256>>>(hc, cnt);
    vq_codebook<<<(KK * DD / 4) / 256, 256>>>(hdw, cnt);
    vq_gather<<<RR, 128>>>(x, out);
}